// round 7
// baseline (speedup 1.0000x reference)
#include <cuda_runtime.h>
#include <cstdint>

// PointerNet_30949534335591 — FINAL (kernel-node config, best sample 4.99us)
//
// Output identity (exact, rel_err = 0.0 across all 6 rounds): the decoder's
// logits are [B, 1]; argmax over the length-1 axis is identically 0. The
// output is a constant zero [B, S] int32 tensor; the entire encoder/decoder
// LSTM stack (~110 GFLOP) is dead code w.r.t. the output. d_out is poisoned
// to 0xAA before timing, so all 512 KB must be written on every replay —
// this is the minimum correct write set.
//
// Performance model (final, validated R1-R6):
//   - Real memory work: 512 KB of stores ~= 0.06 us.
//   - Measured: GPU launch-to-complete 3.7 us (ncu; fixed launch latency at
//     unramped clocks, independent of grid 64 vs 128) + ~1.3 us host graph
//     replay overhead -> 5.0-6.0 us band, width = cross-session drift.
//   - Samples: kernel node 5.79, 4.99 (this config); memset node 5.06,
//     5.09, 5.89, 6.05. Kernel node holds the session minimum.
//   - No remaining source lever: regs=16 (floor), one wave, unpredicated
//     16B stores, no barriers, no smaller write set possible.
//
// 64 CTAs x 256 threads x 2 int4 = 131072 int32 = 512 KB, exact cover.

__global__ void __launch_bounds__(256, 1)
pointer_net_zero2(int4* __restrict__ out) {
    int idx = (blockIdx.x * 256 + threadIdx.x) * 2;
    const int4 z = make_int4(0, 0, 0, 0);
    out[idx]     = z;
    out[idx + 1] = z;
}

__global__ void pointer_net_zero_generic(int* __restrict__ out, int n) {
    int idx = blockIdx.x * blockDim.x + threadIdx.x;
    if (idx < n) out[idx] = 0;
}

extern "C" void kernel_launch(void* const* d_in, const int* in_sizes, int n_in,
                              void* d_out, int out_size) {
    (void)d_in; (void)in_sizes; (void)n_in;

    uintptr_t p = reinterpret_cast<uintptr_t>(d_out);
    if (out_size == 131072 && (p & 0xF) == 0) {
        // Exact expected shape: B*S = 256*512. One wave, unpredicated stores.
        pointer_net_zero2<<<64, 256>>>(reinterpret_cast<int4*>(d_out));
    } else {
        int threads = 256;
        int blocks = (out_size + threads - 1) / threads;
        pointer_net_zero_generic<<<blocks, threads>>>(
            reinterpret_cast<int*>(d_out), out_size);
    }
}